// round 3
// baseline (speedup 1.0000x reference)
#include <cuda_runtime.h>
#include <math.h>

#define BB 8
#define PP 15360
#define QQ 9216
#define HH 96
#define WW 96
#define NMODS 8

#define NCHUNKS 6
#define CHUNK_ROWS 2560          // 94 MB of S per chunk, fits L2
#define QUARTER 2304             // floats per quarter of Q
#define QUARTER4 576             // float4 per quarter
#define FP_ROWS_PER_WARP 4
#define FP_ROWS_PER_CTA 32       // 8 warps * 4 rows
#define BP_ROWS 128
#define BP_CHUNKS_TOT (PP / BP_ROWS)   // 120
#define BP_CHUNKS_PER 20               // per 2560-row chunk

// ---- scratch (static device globals; no allocation anywhere) ----
__device__ __align__(16) float g_sens_part[32 * QQ];
__device__ __align__(16) float g_inv_sens[QQ];
__device__ __align__(16) float g_img[BB * QQ];
__device__ __align__(16) float g_fp_part[4 * PP * 8];
__device__ __align__(16) float g_bp_part[BP_CHUNKS_TOT * BB * QQ];
__device__ __align__(16) float g_em[BB * QQ];
__device__ __align__(16) float g_hidden[BB * 32 * QQ];

// ---- packed f32x2 helpers (FFMA2: only reachable via PTX) ----
__device__ __forceinline__ void fma2(unsigned long long& d,
                                     unsigned long long a,
                                     unsigned long long b) {
    asm("fma.rn.f32x2 %0, %1, %2, %0;" : "+l"(d) : "l"(a), "l"(b));
}
__device__ __forceinline__ float pk_lo(unsigned long long v) {
    return __uint_as_float((unsigned)(v & 0xffffffffu));
}
__device__ __forceinline__ float pk_hi(unsigned long long v) {
    return __uint_as_float((unsigned)(v >> 32));
}
__device__ __forceinline__ unsigned long long splat2(float f) {
    unsigned long long r;
    asm("mov.b64 %0, {%1, %1};" : "=l"(r) : "r"(__float_as_uint(f)));
    return r;
}

// ---- sensitivity image: column sums of S ----
__global__ void k_sens_part(const float* __restrict__ S) {
    int q = blockIdx.x * 256 + threadIdx.x;
    int c = blockIdx.y;
    const float* base = S + (size_t)c * 480 * QQ + q;
    float s = 0.f;
    #pragma unroll 8
    for (int r = 0; r < 480; r++) s += base[(size_t)r * QQ];
    g_sens_part[c * QQ + q] = s;
}

__global__ void k_sens_fin() {
    int q = blockIdx.x * 256 + threadIdx.x;
    float s = 0.f;
    #pragma unroll
    for (int c = 0; c < 32; c++) s += g_sens_part[c * QQ + q];
    g_inv_sens[q] = (s != 0.f) ? 1.f / s : 0.f;
}

__global__ void k_init_img() {
    int n = blockIdx.x * 256 + threadIdx.x;
    g_img[n] = 1.f;
}

// ---- forward projection (quarter-q split): fp_part[qt][p][b] ----
// 256 threads, 8 warps x 4 rows. img quarter staged in smem (72 KB).
__global__ __launch_bounds__(256, 2) void k_fp(const float* __restrict__ S,
                                               int p_base) {
    extern __shared__ ulonglong2 s_img[];   // [8 * 576]
    const int qt = blockIdx.y;

    const ulonglong2* img2 = (const ulonglong2*)g_img;   // 2304 ull2 per batch
    for (int j = threadIdx.x; j < 8 * QUARTER4; j += 256) {
        int b = j / QUARTER4;
        int i = j - b * QUARTER4;
        s_img[j] = img2[b * 2304 + qt * QUARTER4 + i];
    }
    __syncthreads();

    int warp = threadIdx.x >> 5, lane = threadIdx.x & 31;
    int p0 = p_base + blockIdx.x * FP_ROWS_PER_CTA + warp * FP_ROWS_PER_WARP;

    const ulonglong2* row[4];
    #pragma unroll
    for (int r = 0; r < 4; r++)
        row[r] = (const ulonglong2*)(S) + (size_t)(p0 + r) * 2304 + qt * QUARTER4;

    unsigned long long acc[4][8];
    #pragma unroll
    for (int r = 0; r < 4; r++)
        #pragma unroll
        for (int b = 0; b < 8; b++) acc[r][b] = 0ull;

    #pragma unroll 2
    for (int i = lane; i < QUARTER4; i += 32) {
        ulonglong2 sv0 = row[0][i];
        ulonglong2 sv1 = row[1][i];
        ulonglong2 sv2 = row[2][i];
        ulonglong2 sv3 = row[3][i];
        #pragma unroll
        for (int b = 0; b < 8; b++) {
            ulonglong2 iv = s_img[b * QUARTER4 + i];
            fma2(acc[0][b], sv0.x, iv.x); fma2(acc[0][b], sv0.y, iv.y);
            fma2(acc[1][b], sv1.x, iv.x); fma2(acc[1][b], sv1.y, iv.y);
            fma2(acc[2][b], sv2.x, iv.x); fma2(acc[2][b], sv2.y, iv.y);
            fma2(acc[3][b], sv3.x, iv.x); fma2(acc[3][b], sv3.y, iv.y);
        }
    }

    #pragma unroll
    for (int r = 0; r < 4; r++) {
        #pragma unroll
        for (int b = 0; b < 8; b++) {
            float v = pk_lo(acc[r][b]) + pk_hi(acc[r][b]);
            #pragma unroll
            for (int off = 16; off > 0; off >>= 1)
                v += __shfl_xor_sync(0xffffffffu, v, off);
            if (lane == 0)
                g_fp_part[qt * (PP * 8) + (p0 + r) * 8 + b] = v;
        }
    }
}

// ---- backprojection (ratio computed inline): partials per 128-row chunk ----
__global__ __launch_bounds__(256) void k_bp(const float* __restrict__ S,
                                            const float* __restrict__ sino,
                                            int p_base, int chunk_base) {
    __shared__ unsigned long long s_ratio2[BP_ROWS * 8];
    const int p0 = p_base + blockIdx.y * BP_ROWS;

    for (int j = threadIdx.x; j < BP_ROWS * 8; j += 256) {
        int p = p0 + (j >> 3), b = j & 7;
        float fp = g_fp_part[p * 8 + b]
                 + g_fp_part[1 * (PP * 8) + p * 8 + b]
                 + g_fp_part[2 * (PP * 8) + p * 8 + b]
                 + g_fp_part[3 * (PP * 8) + p * 8 + b];
        float rv = (fp > 0.f) ? sino[b * PP + p] / fp : 0.f;
        s_ratio2[j] = splat2(rv);
    }
    __syncthreads();

    const int qi = blockIdx.x * 256 + threadIdx.x;   // ull2 column (16B)
    const ulonglong2* S2 = (const ulonglong2*)S;

    unsigned long long accl[8], acch[8];
    #pragma unroll
    for (int b = 0; b < 8; b++) { accl[b] = 0ull; acch[b] = 0ull; }

    #pragma unroll 4
    for (int r = 0; r < BP_ROWS; r++) {
        ulonglong2 s = S2[(size_t)(p0 + r) * 2304 + qi];
        const unsigned long long* rp = s_ratio2 + r * 8;
        #pragma unroll
        for (int b = 0; b < 8; b++) {
            unsigned long long rv = rp[b];
            fma2(accl[b], s.x, rv);
            fma2(acch[b], s.y, rv);
        }
    }

    float4* bp4 = (float4*)g_bp_part;
    int chunk = chunk_base + blockIdx.y;
    #pragma unroll
    for (int b = 0; b < 8; b++) {
        float4 o;
        o.x = pk_lo(accl[b]); o.y = pk_hi(accl[b]);
        o.z = pk_lo(acch[b]); o.w = pk_hi(acch[b]);
        bp4[(size_t)(chunk * 8 + b) * 2304 + qi] = o;
    }
}

// ---- reduce bp partials + EM image ----
__global__ void k_em() {
    int n = blockIdx.x * 256 + threadIdx.x;
    int q = n % QQ;
    float s = 0.f;
    #pragma unroll 8
    for (int c = 0; c < BP_CHUNKS_TOT; c++)
        s += g_bp_part[(size_t)c * (BB * QQ) + n];
    g_em[n] = g_img[n] * g_inv_sens[q] * s;
}

// ---- conv1: 1->32 3x3 SAME + relu ----
__global__ __launch_bounds__(256) void k_conv1(const float* __restrict__ w1,
                                               const float* __restrict__ b1) {
    __shared__ float s_w[288];
    __shared__ float s_b[32];
    for (int j = threadIdx.x; j < 288; j += 256) s_w[j] = w1[j];
    if (threadIdx.x < 32) s_b[threadIdx.x] = b1[threadIdx.x];
    __syncthreads();

    int n = blockIdx.x * 256 + threadIdx.x;
    int b = n / QQ, rem = n % QQ;
    int y = rem / WW, x = rem % WW;

    float v[9];
    #pragma unroll
    for (int dy = 0; dy < 3; dy++)
        #pragma unroll
        for (int dx = 0; dx < 3; dx++) {
            int yy = y + dy - 1, xx = x + dx - 1;
            v[dy * 3 + dx] = (yy >= 0 && yy < HH && xx >= 0 && xx < WW)
                                 ? g_img[b * QQ + yy * WW + xx] : 0.f;
        }

    #pragma unroll 4
    for (int c = 0; c < 32; c++) {
        float a = s_b[c];
        #pragma unroll
        for (int k = 0; k < 9; k++) a += v[k] * s_w[c * 9 + k];
        g_hidden[(b * 32 + c) * QQ + rem] = fmaxf(a, 0.f);
    }
}

// ---- conv2 (32->1 3x3 SAME) fused with FBSEM fusion ----
__global__ __launch_bounds__(256) void k_conv2f(const float* __restrict__ w2,
                                                const float* __restrict__ b2,
                                                const float* __restrict__ beta,
                                                float* __restrict__ out,
                                                int write_out) {
    __shared__ float s_w[288];
    __shared__ float s_h[10 * 100];
    int b = blockIdx.x / 12, strip = blockIdx.x % 12;
    int y0 = strip * 8;

    for (int j = threadIdx.x; j < 288; j += 256) s_w[j] = w2[j];
    float bias = b2[0];
    float bt = beta[0];

    int py[3], px[3];
    #pragma unroll
    for (int j = 0; j < 3; j++) {
        int pid = threadIdx.x + j * 256;
        py[j] = pid / 96;
        px[j] = pid % 96;
    }
    float acc[3] = {bias, bias, bias};

    for (int c = 0; c < 32; c++) {
        __syncthreads();
        const float* hsrc = g_hidden + (size_t)(b * 32 + c) * QQ;
        for (int j = threadIdx.x; j < 980; j += 256) {
            int ty = j / 98, tx = j % 98;
            int yy = y0 - 1 + ty, xx = tx - 1;
            s_h[ty * 100 + tx] = (yy >= 0 && yy < HH && xx >= 0 && xx < WW)
                                     ? hsrc[yy * WW + xx] : 0.f;
        }
        __syncthreads();
        const float* wc = s_w + c * 9;
        #pragma unroll
        for (int j = 0; j < 3; j++) {
            float a = 0.f;
            #pragma unroll
            for (int dy = 0; dy < 3; dy++)
                #pragma unroll
                for (int dx = 0; dx < 3; dx++)
                    a += s_h[(py[j] + dy) * 100 + px[j] + dx] * wc[dy * 3 + dx];
            acc[j] += a;
        }
    }

    #pragma unroll
    for (int j = 0; j < 3; j++) {
        int yy = y0 + py[j];
        int q = yy * WW + px[j];
        int n = b * QQ + q;
        float inv = g_inv_sens[q];
        float b2i = bt * bt * inv;
        float em = g_em[n];
        float t = 1.f - b2i * acc[j];
        float val = 2.f * em / (t + sqrtf(t * t + 4.f * b2i * em));
        g_img[n] = val;
        if (write_out) out[n] = val;
    }
}

extern "C" void kernel_launch(void* const* d_in, const int* in_sizes, int n_in,
                              void* d_out, int out_size) {
    const float* sino = (const float*)d_in[0];
    const float* S    = (const float*)d_in[1];
    const float* w1   = (const float*)d_in[2];
    const float* b1   = (const float*)d_in[3];
    const float* w2   = (const float*)d_in[4];
    const float* b2   = (const float*)d_in[5];
    const float* beta = (const float*)d_in[6];
    float* out = (float*)d_out;

    static int smem_set = 0;
    if (!smem_set) {
        cudaFuncSetAttribute(k_fp, cudaFuncAttributeMaxDynamicSharedMemorySize,
                             8 * QUARTER4 * (int)sizeof(ulonglong2));
        smem_set = 1;
    }
    const int fp_smem = 8 * QUARTER4 * (int)sizeof(ulonglong2);   // 73728 B

    k_sens_part<<<dim3(36, 32), 256>>>(S);
    k_sens_fin<<<36, 256>>>();
    k_init_img<<<288, 256>>>();

    for (int it = 0; it < NMODS; it++) {
        for (int c = 0; c < NCHUNKS; c++) {
            int p_base = c * CHUNK_ROWS;
            k_fp<<<dim3(CHUNK_ROWS / FP_ROWS_PER_CTA, 4), 256, fp_smem>>>(S, p_base);
            k_bp<<<dim3(9, BP_CHUNKS_PER), 256>>>(S, sino, p_base,
                                                  c * BP_CHUNKS_PER);
        }
        k_em<<<288, 256>>>();
        k_conv1<<<288, 256>>>(w1, b1);
        k_conv2f<<<96, 256>>>(w2, b2, beta, out, (it == NMODS - 1) ? 1 : 0);
    }
}

// round 4
// speedup vs baseline: 2.2722x; 2.2722x over previous
#include <cuda_runtime.h>
#include <math.h>

#define BB 8
#define PP 15360
#define QQ 9216
#define HH 96
#define WW 96
#define NMODS 8

#define QUARTER4 576               // ull2 (16B) per quarter of a row
#define FP_ROWS_PER_CTA 16         // 8 warps * 2 rows
#define BP_ROWS 240
#define BP_CHUNKS 64               // 64 * 240 = 15360

// ---- scratch (static device globals; no allocation anywhere) ----
__device__ __align__(16) float g_sens_part[BP_CHUNKS * QQ];
__device__ __align__(16) float g_inv_sens[QQ];
__device__ __align__(16) float g_img[BB * QQ];
__device__ __align__(16) float g_fp_part[4 * PP * 8];
__device__ __align__(16) float g_bp_part[BP_CHUNKS * BB * QQ];
__device__ __align__(16) float g_em[BB * QQ];
__device__ __align__(16) float g_hidden[BB * 32 * QQ];

// ---- packed f32x2 helpers (FFMA2 only reachable via PTX) ----
__device__ __forceinline__ void fma2(unsigned long long& d,
                                     unsigned long long a,
                                     unsigned long long b) {
    asm("fma.rn.f32x2 %0, %1, %2, %0;" : "+l"(d) : "l"(a), "l"(b));
}
__device__ __forceinline__ float pk_lo(unsigned long long v) {
    return __uint_as_float((unsigned)(v & 0xffffffffu));
}
__device__ __forceinline__ float pk_hi(unsigned long long v) {
    return __uint_as_float((unsigned)(v >> 32));
}
__device__ __forceinline__ unsigned long long splat2(float f) {
    unsigned long long r;
    asm("mov.b64 %0, {%1, %1};" : "=l"(r) : "r"(__float_as_uint(f)));
    return r;
}

__global__ void k_init_img() {
    int n = blockIdx.x * 256 + threadIdx.x;
    g_img[n] = 1.f;
}

// ---- forward projection (quarter-q split): fp_part[qt][p][b] ----
// 256 threads, 8 warps x 2 rows, img quarter staged in smem (72 KB), 3 CTAs/SM.
__global__ __launch_bounds__(256, 3) void k_fp(const float* __restrict__ S) {
    extern __shared__ ulonglong2 s_img[];   // [8 * 576]
    const int qt = blockIdx.y;

    const ulonglong2* img2 = (const ulonglong2*)g_img;   // 2304 ull2 per batch
    #pragma unroll
    for (int j = threadIdx.x; j < 8 * QUARTER4; j += 256) {
        int b = j / QUARTER4;
        int i = j - b * QUARTER4;
        s_img[j] = img2[b * 2304 + qt * QUARTER4 + i];
    }
    __syncthreads();

    const int warp = threadIdx.x >> 5, lane = threadIdx.x & 31;
    const int p0 = blockIdx.x * FP_ROWS_PER_CTA + warp * 2;

    const ulonglong2* rowA =
        (const ulonglong2*)S + (size_t)p0 * 2304 + qt * QUARTER4;
    const ulonglong2* rowB = rowA + 2304;

    unsigned long long acc[2][8];
    #pragma unroll
    for (int r = 0; r < 2; r++)
        #pragma unroll
        for (int b = 0; b < 8; b++) acc[r][b] = 0ull;

    // distance-1 prefetch pipeline over 18 steps (576 / 32)
    ulonglong2 ca = rowA[lane];
    ulonglong2 cb = rowB[lane];
    #pragma unroll
    for (int k = 0; k < 18; k++) {
        ulonglong2 na, nb;
        if (k < 17) {
            na = rowA[lane + (k + 1) * 32];
            nb = rowB[lane + (k + 1) * 32];
        }
        const int i = lane + k * 32;
        #pragma unroll
        for (int b = 0; b < 8; b++) {
            ulonglong2 iv = s_img[b * QUARTER4 + i];
            fma2(acc[0][b], ca.x, iv.x); fma2(acc[0][b], ca.y, iv.y);
            fma2(acc[1][b], cb.x, iv.x); fma2(acc[1][b], cb.y, iv.y);
        }
        ca = na; cb = nb;
    }

    #pragma unroll
    for (int r = 0; r < 2; r++) {
        #pragma unroll
        for (int b = 0; b < 8; b++) {
            float v = pk_lo(acc[r][b]) + pk_hi(acc[r][b]);
            #pragma unroll
            for (int off = 16; off > 0; off >>= 1)
                v += __shfl_xor_sync(0xffffffffu, v, off);
            if (lane == 0)
                g_fp_part[qt * (PP * 8) + (p0 + r) * 8 + b] = v;
        }
    }
}

// ---- backprojection (ratio inline): partials per 240-row chunk ----
// WITH_SENS=1 on iteration 0 additionally accumulates column sums of S.
template <int WITH_SENS>
__global__ __launch_bounds__(256, 4) void k_bp(const float* __restrict__ S,
                                               const float* __restrict__ sino) {
    __shared__ unsigned long long s_ratio[BP_ROWS * 8];
    const int p0 = blockIdx.y * BP_ROWS;

    for (int j = threadIdx.x; j < BP_ROWS * 8; j += 256) {
        int p = p0 + (j >> 3), b = j & 7;
        float fp = g_fp_part[p * 8 + b]
                 + g_fp_part[1 * (PP * 8) + p * 8 + b]
                 + g_fp_part[2 * (PP * 8) + p * 8 + b]
                 + g_fp_part[3 * (PP * 8) + p * 8 + b];
        float rv = (fp > 0.f) ? sino[b * PP + p] / fp : 0.f;
        s_ratio[j] = splat2(rv);
    }
    __syncthreads();

    const int qi = blockIdx.x * 256 + threadIdx.x;   // ull2 column (16B)
    const ulonglong2* S2 = (const ulonglong2*)S;

    unsigned long long accl[8], acch[8];
    #pragma unroll
    for (int b = 0; b < 8; b++) { accl[b] = 0ull; acch[b] = 0ull; }
    unsigned long long sl = 0ull, sh = 0ull;
    const unsigned long long one2 = 0x3f8000003f800000ull;   // {1.f, 1.f}

    ulonglong2 cur = S2[(size_t)p0 * 2304 + qi];
    #pragma unroll 4
    for (int r = 0; r < BP_ROWS; r++) {
        ulonglong2 nxt;
        if (r < BP_ROWS - 1) nxt = S2[(size_t)(p0 + r + 1) * 2304 + qi];
        const unsigned long long* rp = s_ratio + r * 8;
        #pragma unroll
        for (int b = 0; b < 8; b++) {
            fma2(accl[b], cur.x, rp[b]);
            fma2(acch[b], cur.y, rp[b]);
        }
        if (WITH_SENS) { fma2(sl, cur.x, one2); fma2(sh, cur.y, one2); }
        cur = nxt;
    }

    float4* bp4 = (float4*)g_bp_part;
    const int chunk = blockIdx.y;
    #pragma unroll
    for (int b = 0; b < 8; b++) {
        float4 o;
        o.x = pk_lo(accl[b]); o.y = pk_hi(accl[b]);
        o.z = pk_lo(acch[b]); o.w = pk_hi(acch[b]);
        bp4[(size_t)(chunk * 8 + b) * 2304 + qi] = o;
    }
    if (WITH_SENS) {
        float4 o;
        o.x = pk_lo(sl); o.y = pk_hi(sl);
        o.z = pk_lo(sh); o.w = pk_hi(sh);
        ((float4*)g_sens_part)[(size_t)chunk * 2304 + qi] = o;
    }
}

// ---- reduce bp partials + EM image (iter 0 also finalizes inv_sens) ----
__global__ void k_em(int first) {
    int n = blockIdx.x * 256 + threadIdx.x;
    int q = n % QQ;
    float inv;
    if (first) {
        float sv = 0.f;
        #pragma unroll 8
        for (int c = 0; c < BP_CHUNKS; c++) sv += g_sens_part[c * QQ + q];
        inv = (sv != 0.f) ? 1.f / sv : 0.f;
        g_inv_sens[q] = inv;   // 8 threads (one per batch) write identical value
    } else {
        inv = g_inv_sens[q];
    }
    float s = 0.f;
    #pragma unroll 8
    for (int c = 0; c < BP_CHUNKS; c++)
        s += g_bp_part[(size_t)c * (BB * QQ) + n];
    g_em[n] = g_img[n] * inv * s;
}

// ---- conv1: 1->32 3x3 SAME + relu ----
__global__ __launch_bounds__(256) void k_conv1(const float* __restrict__ w1,
                                               const float* __restrict__ b1) {
    __shared__ float s_w[288];
    __shared__ float s_b[32];
    for (int j = threadIdx.x; j < 288; j += 256) s_w[j] = w1[j];
    if (threadIdx.x < 32) s_b[threadIdx.x] = b1[threadIdx.x];
    __syncthreads();

    int n = blockIdx.x * 256 + threadIdx.x;
    int b = n / QQ, rem = n % QQ;
    int y = rem / WW, x = rem % WW;

    float v[9];
    #pragma unroll
    for (int dy = 0; dy < 3; dy++)
        #pragma unroll
        for (int dx = 0; dx < 3; dx++) {
            int yy = y + dy - 1, xx = x + dx - 1;
            v[dy * 3 + dx] = (yy >= 0 && yy < HH && xx >= 0 && xx < WW)
                                 ? g_img[b * QQ + yy * WW + xx] : 0.f;
        }

    #pragma unroll 4
    for (int c = 0; c < 32; c++) {
        float a = s_b[c];
        #pragma unroll
        for (int k = 0; k < 9; k++) a += v[k] * s_w[c * 9 + k];
        g_hidden[(b * 32 + c) * QQ + rem] = fmaxf(a, 0.f);
    }
}

// ---- conv2 (32->1 3x3 SAME) fused with FBSEM fusion ----
// 192 CTAs: (batch, strip-of-4-rows). 384 threads = one pixel each.
__global__ __launch_bounds__(384) void k_conv2f(const float* __restrict__ w2,
                                                const float* __restrict__ b2,
                                                const float* __restrict__ beta,
                                                float* __restrict__ out,
                                                int write_out) {
    __shared__ float s_w[288];
    __shared__ float s_h[6 * 100];
    const int b = blockIdx.x / 24, strip = blockIdx.x % 24;
    const int y0 = strip * 4;

    if (threadIdx.x < 288) s_w[threadIdx.x] = w2[threadIdx.x];
    const float bias = b2[0];
    const float bt = beta[0];

    const int py = threadIdx.x / 96;
    const int px = threadIdx.x % 96;
    float acc = bias;

    for (int c = 0; c < 32; c++) {
        __syncthreads();
        const float* hsrc = g_hidden + (size_t)(b * 32 + c) * QQ;
        for (int j = threadIdx.x; j < 588; j += 384) {
            int ty = j / 98, tx = j % 98;
            int yy = y0 - 1 + ty, xx = tx - 1;
            s_h[ty * 100 + tx] = (yy >= 0 && yy < HH && xx >= 0 && xx < WW)
                                     ? hsrc[yy * WW + xx] : 0.f;
        }
        __syncthreads();
        const float* wc = s_w + c * 9;
        float a = 0.f;
        #pragma unroll
        for (int dy = 0; dy < 3; dy++)
            #pragma unroll
            for (int dx = 0; dx < 3; dx++)
                a += s_h[(py + dy) * 100 + px + dx] * wc[dy * 3 + dx];
        acc += a;
    }

    const int q = (y0 + py) * WW + px;
    const int n = b * QQ + q;
    const float inv = g_inv_sens[q];
    const float b2i = bt * bt * inv;
    const float em = g_em[n];
    const float t = 1.f - b2i * acc;
    const float val = 2.f * em / (t + sqrtf(t * t + 4.f * b2i * em));
    g_img[n] = val;
    if (write_out) out[n] = val;
}

extern "C" void kernel_launch(void* const* d_in, const int* in_sizes, int n_in,
                              void* d_out, int out_size) {
    const float* sino = (const float*)d_in[0];
    const float* S    = (const float*)d_in[1];
    const float* w1   = (const float*)d_in[2];
    const float* b1   = (const float*)d_in[3];
    const float* w2   = (const float*)d_in[4];
    const float* b2   = (const float*)d_in[5];
    const float* beta = (const float*)d_in[6];
    float* out = (float*)d_out;

    const int fp_smem = 8 * QUARTER4 * (int)sizeof(ulonglong2);   // 73728 B
    cudaFuncSetAttribute(k_fp, cudaFuncAttributeMaxDynamicSharedMemorySize,
                         fp_smem);

    k_init_img<<<288, 256>>>();

    for (int it = 0; it < NMODS; it++) {
        k_fp<<<dim3(PP / FP_ROWS_PER_CTA, 4), 256, fp_smem>>>(S);
        if (it == 0)
            k_bp<1><<<dim3(9, BP_CHUNKS), 256>>>(S, sino);
        else
            k_bp<0><<<dim3(9, BP_CHUNKS), 256>>>(S, sino);
        k_em<<<288, 256>>>(it == 0 ? 1 : 0);
        k_conv1<<<288, 256>>>(w1, b1);
        k_conv2f<<<192, 384>>>(w2, b2, beta, out, (it == NMODS - 1) ? 1 : 0);
    }
}

// round 5
// speedup vs baseline: 2.6605x; 1.1709x over previous
#include <cuda_runtime.h>
#include <math.h>

#define BB 8
#define PP 15360
#define QQ 9216
#define HH 96
#define WW 96
#define NMODS 8

#define QUARTER4 576               // ull2 (16B) per quarter of a row
#define FP_RPW 3                   // rows per warp
#define FP_ROWS_PER_CTA 24         // 8 warps * 3 rows
#define BP_ROWS 240
#define BP_CHUNKS 64               // 64 * 240 = 15360

// ---- scratch (static device globals; no allocation anywhere) ----
__device__ __align__(16) float g_sens_part[BP_CHUNKS * QQ];
__device__ __align__(16) float g_inv_sens[QQ];
__device__ __align__(16) float g_img[BB * QQ];
__device__ __align__(16) float g_fp_part[4 * PP * 8];
__device__ __align__(16) float g_bp_part[BP_CHUNKS * BB * QQ];
__device__ __align__(16) float g_em[BB * QQ];
__device__ __align__(16) float g_hidden[BB * 32 * QQ];

// ---- packed f32x2 helpers (FFMA2 only reachable via PTX) ----
__device__ __forceinline__ void fma2(unsigned long long& d,
                                     unsigned long long a,
                                     unsigned long long b) {
    asm("fma.rn.f32x2 %0, %1, %2, %0;" : "+l"(d) : "l"(a), "l"(b));
}
__device__ __forceinline__ float pk_lo(unsigned long long v) {
    return __uint_as_float((unsigned)(v & 0xffffffffu));
}
__device__ __forceinline__ float pk_hi(unsigned long long v) {
    return __uint_as_float((unsigned)(v >> 32));
}
__device__ __forceinline__ unsigned long long splat2(float f) {
    unsigned long long r;
    asm("mov.b64 %0, {%1, %1};" : "=l"(r) : "r"(__float_as_uint(f)));
    return r;
}

__global__ void k_init_img() {
    int n = blockIdx.x * 256 + threadIdx.x;
    g_img[n] = 1.f;
}

// ---- forward projection (quarter-q split): fp_part[qt][p][b] ----
// 256 threads, 8 warps x 3 rows, img quarter staged in smem (72 KB), 2 CTAs/SM.
__global__ __launch_bounds__(256, 2) void k_fp(const float* __restrict__ S) {
    extern __shared__ ulonglong2 s_img[];   // [8 * 576]
    const int qt = blockIdx.y;

    const ulonglong2* img2 = (const ulonglong2*)g_img;   // 2304 ull2 per batch
    #pragma unroll
    for (int j = threadIdx.x; j < 8 * QUARTER4; j += 256) {
        int b = j / QUARTER4;
        int i = j - b * QUARTER4;
        s_img[j] = img2[b * 2304 + qt * QUARTER4 + i];
    }
    __syncthreads();

    const int warp = threadIdx.x >> 5, lane = threadIdx.x & 31;
    const int p0 = blockIdx.x * FP_ROWS_PER_CTA + warp * FP_RPW;

    const ulonglong2* r0 =
        (const ulonglong2*)S + (size_t)p0 * 2304 + qt * QUARTER4;
    const ulonglong2* r1 = r0 + 2304;
    const ulonglong2* r2 = r0 + 4608;

    unsigned long long acc[3][8];
    #pragma unroll
    for (int r = 0; r < 3; r++)
        #pragma unroll
        for (int b = 0; b < 8; b++) acc[r][b] = 0ull;

    // distance-1 prefetch pipeline over 18 steps (576 / 32)
    ulonglong2 c0 = r0[lane];
    ulonglong2 c1 = r1[lane];
    ulonglong2 c2 = r2[lane];
    #pragma unroll
    for (int k = 0; k < 18; k++) {
        ulonglong2 n0, n1, n2;
        if (k < 17) {
            n0 = r0[lane + (k + 1) * 32];
            n1 = r1[lane + (k + 1) * 32];
            n2 = r2[lane + (k + 1) * 32];
        }
        const int i = lane + k * 32;
        #pragma unroll
        for (int b = 0; b < 8; b++) {
            ulonglong2 iv = s_img[b * QUARTER4 + i];
            fma2(acc[0][b], c0.x, iv.x); fma2(acc[0][b], c0.y, iv.y);
            fma2(acc[1][b], c1.x, iv.x); fma2(acc[1][b], c1.y, iv.y);
            fma2(acc[2][b], c2.x, iv.x); fma2(acc[2][b], c2.y, iv.y);
        }
        c0 = n0; c1 = n1; c2 = n2;
    }

    #pragma unroll
    for (int r = 0; r < 3; r++) {
        #pragma unroll
        for (int b = 0; b < 8; b++) {
            float v = pk_lo(acc[r][b]) + pk_hi(acc[r][b]);
            #pragma unroll
            for (int off = 16; off > 0; off >>= 1)
                v += __shfl_xor_sync(0xffffffffu, v, off);
            if (lane == 0)
                g_fp_part[qt * (PP * 8) + (p0 + r) * 8 + b] = v;
        }
    }
}

// ---- backprojection (ratio inline): partials per 240-row chunk ----
// WITH_SENS=1 on iteration 0 additionally accumulates column sums of S.
template <int WITH_SENS>
__global__ __launch_bounds__(256, 4) void k_bp(const float* __restrict__ S,
                                               const float* __restrict__ sino) {
    __shared__ ulonglong2 s_ratio[BP_ROWS * 4];   // [row][bpair], 16B aligned
    const int p0 = blockIdx.y * BP_ROWS;

    for (int j = threadIdx.x; j < BP_ROWS * 8; j += 256) {
        int p = p0 + (j >> 3), b = j & 7;
        float fp = g_fp_part[p * 8 + b]
                 + g_fp_part[1 * (PP * 8) + p * 8 + b]
                 + g_fp_part[2 * (PP * 8) + p * 8 + b]
                 + g_fp_part[3 * (PP * 8) + p * 8 + b];
        float rv = (fp > 0.f) ? sino[b * PP + p] / fp : 0.f;
        ((unsigned long long*)s_ratio)[j] = splat2(rv);
    }
    __syncthreads();

    const int qi = blockIdx.x * 256 + threadIdx.x;   // ull2 column (16B)
    const ulonglong2* S2 = (const ulonglong2*)S;

    unsigned long long accl[8], acch[8];
    #pragma unroll
    for (int b = 0; b < 8; b++) { accl[b] = 0ull; acch[b] = 0ull; }
    unsigned long long sl = 0ull, sh = 0ull;
    const unsigned long long one2 = 0x3f8000003f800000ull;   // {1.f, 1.f}

    // distance-2 prefetch pipeline
    ulonglong2 cur = S2[(size_t)p0 * 2304 + qi];
    ulonglong2 nx1 = S2[(size_t)(p0 + 1) * 2304 + qi];
    #pragma unroll 4
    for (int r = 0; r < BP_ROWS; r++) {
        ulonglong2 nx2;
        if (r < BP_ROWS - 2) nx2 = S2[(size_t)(p0 + r + 2) * 2304 + qi];
        const ulonglong2* rp = s_ratio + r * 4;
        ulonglong2 q0 = rp[0], q1 = rp[1], q2 = rp[2], q3 = rp[3];
        fma2(accl[0], cur.x, q0.x); fma2(acch[0], cur.y, q0.x);
        fma2(accl[1], cur.x, q0.y); fma2(acch[1], cur.y, q0.y);
        fma2(accl[2], cur.x, q1.x); fma2(acch[2], cur.y, q1.x);
        fma2(accl[3], cur.x, q1.y); fma2(acch[3], cur.y, q1.y);
        fma2(accl[4], cur.x, q2.x); fma2(acch[4], cur.y, q2.x);
        fma2(accl[5], cur.x, q2.y); fma2(acch[5], cur.y, q2.y);
        fma2(accl[6], cur.x, q3.x); fma2(acch[6], cur.y, q3.x);
        fma2(accl[7], cur.x, q3.y); fma2(acch[7], cur.y, q3.y);
        if (WITH_SENS) { fma2(sl, cur.x, one2); fma2(sh, cur.y, one2); }
        cur = nx1; nx1 = nx2;
    }

    float4* bp4 = (float4*)g_bp_part;
    const int chunk = blockIdx.y;
    #pragma unroll
    for (int b = 0; b < 8; b++) {
        float4 o;
        o.x = pk_lo(accl[b]); o.y = pk_hi(accl[b]);
        o.z = pk_lo(acch[b]); o.w = pk_hi(acch[b]);
        bp4[(size_t)(chunk * 8 + b) * 2304 + qi] = o;
    }
    if (WITH_SENS) {
        float4 o;
        o.x = pk_lo(sl); o.y = pk_hi(sl);
        o.z = pk_lo(sh); o.w = pk_hi(sh);
        ((float4*)g_sens_part)[(size_t)chunk * 2304 + qi] = o;
    }
}

// ---- fused: reduce bp partials -> em image, then conv1 (1->32 3x3+relu) ----
__global__ __launch_bounds__(256) void k_emc1(const float* __restrict__ w1,
                                              const float* __restrict__ b1,
                                              int first) {
    __shared__ float s_w[288];
    __shared__ float s_b[32];
    for (int j = threadIdx.x; j < 288; j += 256) s_w[j] = w1[j];
    if (threadIdx.x < 32) s_b[threadIdx.x] = b1[threadIdx.x];
    __syncthreads();

    const int n = blockIdx.x * 256 + threadIdx.x;
    const int q = n % QQ;
    const int b = n / QQ;

    float inv;
    if (first) {
        float sv = 0.f;
        #pragma unroll 16
        for (int c = 0; c < BP_CHUNKS; c++) sv += g_sens_part[c * QQ + q];
        inv = (sv != 0.f) ? 1.f / sv : 0.f;
        g_inv_sens[q] = inv;   // 8 threads write identical value
    } else {
        inv = g_inv_sens[q];
    }
    float s = 0.f;
    #pragma unroll 16
    for (int c = 0; c < BP_CHUNKS; c++)
        s += g_bp_part[(size_t)c * (BB * QQ) + n];
    g_em[n] = g_img[n] * inv * s;

    // conv1 for this pixel (uses pre-update img; independent of em)
    const int y = q / WW, x = q % WW;
    float v[9];
    #pragma unroll
    for (int dy = 0; dy < 3; dy++)
        #pragma unroll
        for (int dx = 0; dx < 3; dx++) {
            int yy = y + dy - 1, xx = x + dx - 1;
            v[dy * 3 + dx] = (yy >= 0 && yy < HH && xx >= 0 && xx < WW)
                                 ? g_img[b * QQ + yy * WW + xx] : 0.f;
        }
    #pragma unroll 4
    for (int c = 0; c < 32; c++) {
        float a = s_b[c];
        #pragma unroll
        for (int k = 0; k < 9; k++) a += v[k] * s_w[c * 9 + k];
        g_hidden[(b * 32 + c) * QQ + q] = fmaxf(a, 0.f);
    }
}

// ---- conv2 (32->1 3x3 SAME) fused with FBSEM fusion ----
__global__ __launch_bounds__(384) void k_conv2f(const float* __restrict__ w2,
                                                const float* __restrict__ b2,
                                                const float* __restrict__ beta,
                                                float* __restrict__ out,
                                                int write_out) {
    __shared__ float s_w[288];
    __shared__ float s_h[6 * 100];
    const int b = blockIdx.x / 24, strip = blockIdx.x % 24;
    const int y0 = strip * 4;

    if (threadIdx.x < 288) s_w[threadIdx.x] = w2[threadIdx.x];
    const float bias = b2[0];
    const float bt = beta[0];

    const int py = threadIdx.x / 96;
    const int px = threadIdx.x % 96;
    float acc = bias;

    for (int c = 0; c < 32; c++) {
        __syncthreads();
        const float* hsrc = g_hidden + (size_t)(b * 32 + c) * QQ;
        for (int j = threadIdx.x; j < 588; j += 384) {
            int ty = j / 98, tx = j % 98;
            int yy = y0 - 1 + ty, xx = tx - 1;
            s_h[ty * 100 + tx] = (yy >= 0 && yy < HH && xx >= 0 && xx < WW)
                                     ? hsrc[yy * WW + xx] : 0.f;
        }
        __syncthreads();
        const float* wc = s_w + c * 9;
        float a = 0.f;
        #pragma unroll
        for (int dy = 0; dy < 3; dy++)
            #pragma unroll
            for (int dx = 0; dx < 3; dx++)
                a += s_h[(py + dy) * 100 + px + dx] * wc[dy * 3 + dx];
        acc += a;
    }

    const int q = (y0 + py) * WW + px;
    const int n = b * QQ + q;
    const float inv = g_inv_sens[q];
    const float b2i = bt * bt * inv;
    const float em = g_em[n];
    const float t = 1.f - b2i * acc;
    const float val = 2.f * em / (t + sqrtf(t * t + 4.f * b2i * em));
    g_img[n] = val;
    if (write_out) out[n] = val;
}

extern "C" void kernel_launch(void* const* d_in, const int* in_sizes, int n_in,
                              void* d_out, int out_size) {
    const float* sino = (const float*)d_in[0];
    const float* S    = (const float*)d_in[1];
    const float* w1   = (const float*)d_in[2];
    const float* b1   = (const float*)d_in[3];
    const float* w2   = (const float*)d_in[4];
    const float* b2   = (const float*)d_in[5];
    const float* beta = (const float*)d_in[6];
    float* out = (float*)d_out;

    const int fp_smem = 8 * QUARTER4 * (int)sizeof(ulonglong2);   // 73728 B
    cudaFuncSetAttribute(k_fp, cudaFuncAttributeMaxDynamicSharedMemorySize,
                         fp_smem);

    k_init_img<<<288, 256>>>();

    for (int it = 0; it < NMODS; it++) {
        k_fp<<<dim3(PP / FP_ROWS_PER_CTA, 4), 256, fp_smem>>>(S);
        if (it == 0)
            k_bp<1><<<dim3(9, BP_CHUNKS), 256>>>(S, sino);
        else
            k_bp<0><<<dim3(9, BP_CHUNKS), 256>>>(S, sino);
        k_emc1<<<288, 256>>>(w1, b1, it == 0 ? 1 : 0);
        k_conv2f<<<192, 384>>>(w2, b2, beta, out, (it == NMODS - 1) ? 1 : 0);
    }
}